// round 2
// baseline (speedup 1.0000x reference)
#include <cuda_runtime.h>
#include <cstdint>

// ---------------------------------------------------------------------------
// PointNet++ (3 SA stages) forward for B=64, N=4096 input, fp32.
// Round 2: packed fp32x2 FMA (FFMA2) in the MLP inner loops, o-major padded
// weights (LDG.128 weight fetch), merged BN-fold kernel.
// ---------------------------------------------------------------------------

static constexpr int B   = 64;
static constexpr int N0  = 4096;
static constexpr int S0  = 128, NSAMP0 = 32;
static constexpr int S1  = 64;
static constexpr int S2  = 32;

// ------------------------- device scratch (no allocs) ----------------------
__device__ float g_nx1[B * S0 * 3];
__device__ float g_nx2[B * S1 * 3];
__device__ float g_nx3[B * S2 * 3];
__device__ int   g_idxbuf[B * S0 * NSAMP0];
__device__ float g_f1[B * S0 * 64];
__device__ float g_f2[B * S1 * 128];

// o-major, k padded to multiple of 4 (zeros in pad)
__device__ __align__(16) float g_w0S[32  * 12];   __device__ float g_b0[32];
__device__ __align__(16) float g_w1S[64  * 32];   __device__ float g_b1[64];
__device__ __align__(16) float g_w2S[128 * 68];   __device__ float g_b2[128];
__device__ __align__(16) float g_w3S[128 * 128];  __device__ float g_b3[128];
__device__ __align__(16) float g_w4S[256 * 132];  __device__ float g_b4[256];
__device__ __align__(16) float g_w5S[256 * 256];  __device__ float g_b5[256];

// ------------------------- f32x2 helpers -----------------------------------
typedef unsigned long long u64;

__device__ __forceinline__ u64 pack2(float x) {
    u64 r;
    asm("mov.b64 %0, {%1, %2};" : "=l"(r) : "f"(x), "f"(x));
    return r;
}
__device__ __forceinline__ void unpack2(u64 v, float& lo, float& hi) {
    asm("mov.b64 {%0, %1}, %2;" : "=f"(lo), "=f"(hi) : "l"(v));
}
__device__ __forceinline__ u64 ffma2(u64 a, u64 b, u64 c) {
    u64 d;
    asm("fma.rn.f32x2 %0, %1, %2, %3;" : "=l"(d) : "l"(a), "l"(b), "l"(c));
    return d;
}

// ------------------------- merged BN fold ----------------------------------
// gridDim.y = layer. wS[o*cin4 + k] = w[o*cin + k] * g[o]*rsqrt(rv[o]+eps),
// zero pad for k in [cin, cin4). bias = be - s*rm.
struct FoldArgs {
    const float* w[6]; const float* g[6]; const float* be[6];
    const float* rm[6]; const float* rv[6];
    float* wS[6]; float* bias[6];
    int cin[6]; int cin4[6]; int cout[6];
};

__global__ void fold_all_kernel(FoldArgs a)
{
    int l = blockIdx.y;
    int cin = a.cin[l], cin4 = a.cin4[l], cout = a.cout[l];
    const float* w = a.w[l]; const float* g = a.g[l]; const float* be = a.be[l];
    const float* rm = a.rm[l]; const float* rv = a.rv[l];
    float* wS = a.wS[l]; float* bias = a.bias[l];
    int tot = cout * cin4;
    int i = blockIdx.x * blockDim.x + threadIdx.x;
    if (i < cout) {
        float s = g[i] * rsqrtf(rv[i] + 1e-5f);
        bias[i] = be[i] - s * rm[i];
    }
    for (int e = i; e < tot; e += gridDim.x * blockDim.x) {
        int o = e / cin4, k = e - o * cin4;
        float s = g[o] * rsqrtf(rv[o] + 1e-5f);
        wS[e] = (k < cin) ? w[o * cin + k] * s : 0.0f;
    }
}

// ------------------------- farthest point sampling -------------------------
template<int N, int NPOINT, int T>
__global__ void __launch_bounds__(T) fps_kernel(const float* __restrict__ xyz,
                                                float* __restrict__ newxyz)
{
    constexpr int PPT = N / T;
    int b = blockIdx.x;
    int tid = threadIdx.x;
    const float* x = xyz + (size_t)b * N * 3;

    float px[PPT], py[PPT], pz[PPT], dist[PPT];
#pragma unroll
    for (int i = 0; i < PPT; i++) {
        int p = tid + i * T;
        px[i] = x[p * 3 + 0];
        py[i] = x[p * 3 + 1];
        pz[i] = x[p * 3 + 2];
        dist[i] = 1e10f;
    }

    __shared__ float cur[3];
    __shared__ float wv[T / 32];
    __shared__ int   wi[T / 32];

    if (tid == 0) {
        cur[0] = x[0]; cur[1] = x[1]; cur[2] = x[2];
        float* o = newxyz + (size_t)b * NPOINT * 3;
        o[0] = x[0]; o[1] = x[1]; o[2] = x[2];
    }
    __syncthreads();

    for (int j = 1; j < NPOINT; j++) {
        float cx = cur[0], cy = cur[1], cz = cur[2];
        float bv = -1.0f;
        int   bi = 0x7fffffff;
#pragma unroll
        for (int i = 0; i < PPT; i++) {
            float dx = px[i] - cx, dy = py[i] - cy, dz = pz[i] - cz;
            float d = __fadd_rn(__fadd_rn(__fmul_rn(dx, dx), __fmul_rn(dy, dy)),
                                __fmul_rn(dz, dz));
            float nd = fminf(dist[i], d);
            dist[i] = nd;
            int gidx = tid + i * T;
            if (nd > bv || (nd == bv && gidx < bi)) { bv = nd; bi = gidx; }
        }
#pragma unroll
        for (int off = 16; off > 0; off >>= 1) {
            float ov = __shfl_down_sync(0xffffffffu, bv, off);
            int   oi = __shfl_down_sync(0xffffffffu, bi, off);
            if (ov > bv || (ov == bv && oi < bi)) { bv = ov; bi = oi; }
        }
        if ((tid & 31) == 0) { wv[tid >> 5] = bv; wi[tid >> 5] = bi; }
        __syncthreads();
        if (tid < 32) {
            constexpr int NW = T / 32;
            bv = (tid < NW) ? wv[tid] : -2.0f;
            bi = (tid < NW) ? wi[tid] : 0x7fffffff;
#pragma unroll
            for (int off = 16; off > 0; off >>= 1) {
                float ov = __shfl_down_sync(0xffffffffu, bv, off);
                int   oi = __shfl_down_sync(0xffffffffu, bi, off);
                if (ov > bv || (ov == bv && oi < bi)) { bv = ov; bi = oi; }
            }
            if (tid == 0) {
                const float* p = x + (size_t)bi * 3;
                float nx = p[0], ny = p[1], nz = p[2];
                cur[0] = nx; cur[1] = ny; cur[2] = nz;
                float* o = newxyz + ((size_t)b * NPOINT + j) * 3;
                o[0] = nx; o[1] = ny; o[2] = nz;
            }
        }
        __syncthreads();
    }
}

// ------------------------- ball query --------------------------------------
template<int NS>
__global__ void ballquery_kernel(const float* __restrict__ newxyz,
                                 const float* __restrict__ xyz,
                                 int* __restrict__ idxout,
                                 int N, int S, float rr)
{
    __shared__ int rows[4][NS];
    int lane = threadIdx.x & 31;
    int wip  = threadIdx.x >> 5;
    int q = blockIdx.x * 4 + wip;
    int b = q / S;
    const float* nq = newxyz + (size_t)q * 3;
    float qx = nq[0], qy = nq[1], qz = nq[2];
    const float* x = xyz + (size_t)b * N * 3;
    int* row = rows[wip];
    int cnt = 0;

    for (int base = 0; base < N; base += 32) {
        if (cnt >= NS) break;
        int p = base + lane;
        float dx = x[p * 3 + 0] - qx;
        float dy = x[p * 3 + 1] - qy;
        float dz = x[p * 3 + 2] - qz;
        float d = __fadd_rn(__fadd_rn(__fmul_rn(dx, dx), __fmul_rn(dy, dy)),
                            __fmul_rn(dz, dz));
        bool hit = d < rr;
        unsigned m = __ballot_sync(0xffffffffu, hit);
        if (hit) {
            int pos = cnt + __popc(m & ((1u << lane) - 1u));
            if (pos < NS) row[pos] = p;
        }
        cnt += __popc(m);
    }
    __syncwarp();
    int first = (cnt > 0) ? row[0] : 0;
    for (int t = cnt + lane; t < NS; t += 32) row[t] = first;
    __syncwarp();
    for (int t = lane; t < NS; t += 32) idxout[(size_t)q * NS + t] = row[t];
}

// ------------------------- fused group + MLP(2) + maxpool, f32x2 -----------
// Thread t = output channel. Packed f32x2 accumulators (2 samples per reg),
// weights o-major (4 per LDG.128), smem rows read as 16B broadcasts.
template<int CIN4, int C0, int C1, int NS, int T, bool STAGE0, bool FINAL>
__global__ void __launch_bounds__(T) sa_mlp_kernel(
    const float* __restrict__ xyz, const float* __restrict__ feats,
    const float* __restrict__ newxyz, const int* __restrict__ idx,
    const float* __restrict__ w0S, const float* __restrict__ b0,
    const float* __restrict__ w1S, const float* __restrict__ b1,
    float* __restrict__ out, int N, int S)
{
    constexpr int LD = NS + 4;
    __shared__ __align__(16) float xs[CIN4 * LD];
    __shared__ __align__(16) float mid[C0 * LD];
    constexpr int NP = NS / 2;   // packed accumulators

    int gs = blockIdx.x;
    int b = gs / S, s = gs - b * S;
    int tid = threadIdx.x;
    const int* gi = idx + (size_t)gs * NS;
    float cx = newxyz[gs * 3 + 0], cy = newxyz[gs * 3 + 1], cz = newxyz[gs * 3 + 2];

    for (int n = tid; n < NS; n += T) {
        int id = gi[n];
        const float* p = xyz + ((size_t)b * N + id) * 3;
        float ax = p[0], ay = p[1], az = p[2];
        xs[0 * LD + n] = ax - cx;
        xs[1 * LD + n] = ay - cy;
        xs[2 * LD + n] = az - cz;
        if (STAGE0) {
            xs[3 * LD + n] = ax; xs[4 * LD + n] = ay; xs[5 * LD + n] = az;
            xs[6 * LD + n] = ax; xs[7 * LD + n] = ay; xs[8 * LD + n] = az;
            // zero pad rows 9..11
            xs[9 * LD + n] = 0.f; xs[10 * LD + n] = 0.f; xs[11 * LD + n] = 0.f;
        }
    }
    if constexpr (!STAGE0) {
        constexpr int CFULL = CIN4 - 3;          // feat channels + pad
        for (int e = tid; e < CFULL * NS; e += T) {
            int n = e / CFULL, c = e - n * CFULL;
            int cf_real = CFULL - ((CIN4 % 4 == 0) ? (CIN4 - 3) % 1 : 0); // unused
            (void)cf_real;
            // real feat channels = CIN-3 where CIN4 = pad4(CIN)
            xs[(3 + c) * LD + n] = 0.0f;          // default (pad rows)
        }
        __syncthreads();
        constexpr int CF = (CIN4 == 68) ? 64 : 128;   // stage1: 64, stage2: 128
        for (int e = tid; e < CF * NS; e += T) {
            int n = e / CF, c = e - n * CF;
            xs[(3 + c) * LD + n] = feats[((size_t)b * N + gi[n]) * CF + c];
        }
    }
    __syncthreads();

    // ---- layer 0 ----
    if (tid < C0) {
        u64 acc[NP];
        u64 bb = pack2(b0[tid]);
#pragma unroll
        for (int j = 0; j < NP; j++) acc[j] = bb;
        const float4* wrow = reinterpret_cast<const float4*>(&w0S[tid * CIN4]);
#pragma unroll 2
        for (int k4 = 0; k4 < CIN4 / 4; k4++) {
            float4 wv = wrow[k4];
            float wk[4] = {wv.x, wv.y, wv.z, wv.w};
#pragma unroll
            for (int u = 0; u < 4; u++) {
                u64 w2 = pack2(wk[u]);
                const ulonglong2* xr =
                    reinterpret_cast<const ulonglong2*>(&xs[(4 * k4 + u) * LD]);
#pragma unroll
                for (int j = 0; j < NS / 4; j++) {
                    ulonglong2 v = xr[j];
                    acc[2 * j + 0] = ffma2(w2, v.x, acc[2 * j + 0]);
                    acc[2 * j + 1] = ffma2(w2, v.y, acc[2 * j + 1]);
                }
            }
        }
#pragma unroll
        for (int j = 0; j < NP; j++) {
            float lo, hi;
            unpack2(acc[j], lo, hi);
            mid[tid * LD + 2 * j + 0] = fmaxf(lo, 0.0f);
            mid[tid * LD + 2 * j + 1] = fmaxf(hi, 0.0f);
        }
    }
    __syncthreads();

    // ---- layer 1 + maxpool ----
    if (tid < C1) {
        u64 acc[NP];
        u64 bb = pack2(b1[tid]);
#pragma unroll
        for (int j = 0; j < NP; j++) acc[j] = bb;
        const float4* wrow = reinterpret_cast<const float4*>(&w1S[tid * C0]);
#pragma unroll 2
        for (int k4 = 0; k4 < C0 / 4; k4++) {
            float4 wv = wrow[k4];
            float wk[4] = {wv.x, wv.y, wv.z, wv.w};
#pragma unroll
            for (int u = 0; u < 4; u++) {
                u64 w2 = pack2(wk[u]);
                const ulonglong2* mr =
                    reinterpret_cast<const ulonglong2*>(&mid[(4 * k4 + u) * LD]);
#pragma unroll
                for (int j = 0; j < NS / 4; j++) {
                    ulonglong2 v = mr[j];
                    acc[2 * j + 0] = ffma2(w2, v.x, acc[2 * j + 0]);
                    acc[2 * j + 1] = ffma2(w2, v.y, acc[2 * j + 1]);
                }
            }
        }
        float mx = 0.0f;   // relu clamps at 0 anyway
#pragma unroll
        for (int j = 0; j < NP; j++) {
            float lo, hi;
            unpack2(acc[j], lo, hi);
            mx = fmaxf(mx, fmaxf(lo, hi));
        }
        if (FINAL)
            out[(size_t)b * C1 * S + (size_t)tid * S + s] = mx;   // (B, C, S)
        else
            out[((size_t)b * S + s) * C1 + tid] = mx;             // (B, S, C)
    }
}

// ---------------------------------------------------------------------------
extern "C" void kernel_launch(void* const* d_in, const int* in_sizes, int n_in,
                              void* d_out, int out_size)
{
    (void)in_sizes; (void)n_in; (void)out_size;
    const float* pc = (const float*)d_in[0];

    float *nx1, *nx2, *nx3, *f1, *f2;
    int* idxb;
    float *w0S, *w1S, *w2S, *w3S, *w4S, *w5S;
    float *b0, *b1, *b2, *b3, *b4, *b5;
    cudaGetSymbolAddress((void**)&nx1, g_nx1);
    cudaGetSymbolAddress((void**)&nx2, g_nx2);
    cudaGetSymbolAddress((void**)&nx3, g_nx3);
    cudaGetSymbolAddress((void**)&idxb, g_idxbuf);
    cudaGetSymbolAddress((void**)&f1, g_f1);
    cudaGetSymbolAddress((void**)&f2, g_f2);
    cudaGetSymbolAddress((void**)&w0S, g_w0S); cudaGetSymbolAddress((void**)&b0, g_b0);
    cudaGetSymbolAddress((void**)&w1S, g_w1S); cudaGetSymbolAddress((void**)&b1, g_b1);
    cudaGetSymbolAddress((void**)&w2S, g_w2S); cudaGetSymbolAddress((void**)&b2, g_b2);
    cudaGetSymbolAddress((void**)&w3S, g_w3S); cudaGetSymbolAddress((void**)&b3, g_b3);
    cudaGetSymbolAddress((void**)&w4S, g_w4S); cudaGetSymbolAddress((void**)&b4, g_b4);
    cudaGetSymbolAddress((void**)&w5S, g_w5S); cudaGetSymbolAddress((void**)&b5, g_b5);

    FoldArgs fa;
    const int cins[6]  = {9, 32, 67, 128, 131, 256};
    const int cin4s[6] = {12, 32, 68, 128, 132, 256};
    const int couts[6] = {32, 64, 128, 128, 256, 256};
    float* wSs[6] = {w0S, w1S, w2S, w3S, w4S, w5S};
    float* bss[6] = {b0, b1, b2, b3, b4, b5};
    for (int l = 0; l < 6; l++) {
        fa.w[l]  = (const float*)d_in[1 + 5 * l];
        fa.g[l]  = (const float*)d_in[2 + 5 * l];
        fa.be[l] = (const float*)d_in[3 + 5 * l];
        fa.rm[l] = (const float*)d_in[4 + 5 * l];
        fa.rv[l] = (const float*)d_in[5 + 5 * l];
        fa.wS[l] = wSs[l]; fa.bias[l] = bss[l];
        fa.cin[l] = cins[l]; fa.cin4[l] = cin4s[l]; fa.cout[l] = couts[l];
    }
    fold_all_kernel<<<dim3(72, 6), 256>>>(fa);

    const float rr0 = (float)(0.02 * 0.02);
    const float rr1 = (float)(0.04 * 0.04);
    const float rr2 = (float)(0.08 * 0.08);

    // ---- stage 0: N=4096 -> S=128 ----
    fps_kernel<4096, 128, 256><<<B, 256>>>(pc, nx1);
    ballquery_kernel<32><<<(B * S0) / 4, 128>>>(nx1, pc, idxb, N0, S0, rr0);
    sa_mlp_kernel<12, 32, 64, 32, 64, true, false><<<B * S0, 64>>>(
        pc, nullptr, nx1, idxb, w0S, b0, w1S, b1, f1, N0, S0);

    // ---- stage 1: N=128 -> S=64 ----
    fps_kernel<128, 64, 128><<<B, 128>>>(nx1, nx2);
    ballquery_kernel<32><<<(B * S1) / 4, 128>>>(nx2, nx1, idxb, S0, S1, rr1);
    sa_mlp_kernel<68, 128, 128, 32, 128, false, false><<<B * S1, 128>>>(
        nx1, f1, nx2, idxb, w2S, b2, w3S, b3, f2, S0, S1);

    // ---- stage 2: N=64 -> S=32 ----
    fps_kernel<64, 32, 64><<<B, 64>>>(nx2, nx3);
    ballquery_kernel<16><<<(B * S2) / 4, 128>>>(nx3, nx2, idxb, S1, S2, rr2);
    sa_mlp_kernel<132, 256, 256, 16, 256, false, true><<<B * S2, 256>>>(
        nx2, f2, nx3, idxb, w4S, b4, w5S, b5, (float*)d_out, S1, S2);
}

// round 4
// speedup vs baseline: 1.6330x; 1.6330x over previous
#include <cuda_runtime.h>
#include <cstdint>

// ---------------------------------------------------------------------------
// PointNet++ (3 SA stages), B=64, N=4096, fp32.
// Round 4: R3 design (2-D register tiling, 4 ch x NO samples per thread,
// packed fp32x2 FMA) with the stage-2 final-reduce bug fixed
// (strided channel loop instead of `if (tid < C1)`).
// ---------------------------------------------------------------------------

static constexpr int B   = 64;
static constexpr int N0  = 4096;
static constexpr int S0  = 128, NSAMP0 = 32;
static constexpr int S1  = 64;
static constexpr int S2  = 32;

// ------------------------- device scratch (no allocs) ----------------------
__device__ float g_nx1[B * S0 * 3];
__device__ float g_nx2[B * S1 * 3];
__device__ float g_nx3[B * S2 * 3];
__device__ int   g_idxbuf[B * S0 * NSAMP0];
__device__ float g_f1[B * S0 * 64];
__device__ float g_f2[B * S1 * 128];

// k-major folded weights: wT[k*Cout + o]
__device__ __align__(16) float g_w0T[9 * 32];     __device__ __align__(16) float g_b0[32];
__device__ __align__(16) float g_w1T[32 * 64];    __device__ __align__(16) float g_b1[64];
__device__ __align__(16) float g_w2T[67 * 128];   __device__ __align__(16) float g_b2[128];
__device__ __align__(16) float g_w3T[128 * 128];  __device__ __align__(16) float g_b3[128];
__device__ __align__(16) float g_w4T[131 * 256];  __device__ __align__(16) float g_b4[256];
__device__ __align__(16) float g_w5T[256 * 256];  __device__ __align__(16) float g_b5[256];

// ------------------------- f32x2 helpers -----------------------------------
typedef unsigned long long u64;

__device__ __forceinline__ u64 pack2(float x) {
    u64 r;
    asm("mov.b64 %0, {%1, %2};" : "=l"(r) : "f"(x), "f"(x));
    return r;
}
__device__ __forceinline__ void unpack2(u64 v, float& lo, float& hi) {
    asm("mov.b64 {%0, %1}, %2;" : "=f"(lo), "=f"(hi) : "l"(v));
}
__device__ __forceinline__ u64 ffma2(u64 a, u64 b, u64 c) {
    u64 d;
    asm("fma.rn.f32x2 %0, %1, %2, %3;" : "=l"(d) : "l"(a), "l"(b), "l"(c));
    return d;
}

// ------------------------- merged BN fold (k-major) ------------------------
struct FoldArgs {
    const float* w[6]; const float* g[6]; const float* be[6];
    const float* rm[6]; const float* rv[6];
    float* wT[6]; float* bias[6];
    int cin[6]; int cout[6];
};

__global__ void fold_all_kernel(FoldArgs a)
{
    int l = blockIdx.y;
    int cin = a.cin[l], cout = a.cout[l];
    const float* w = a.w[l]; const float* g = a.g[l]; const float* be = a.be[l];
    const float* rm = a.rm[l]; const float* rv = a.rv[l];
    float* wT = a.wT[l]; float* bias = a.bias[l];
    int tot = cout * cin;
    int i = blockIdx.x * blockDim.x + threadIdx.x;
    if (i < cout) {
        float s = g[i] * rsqrtf(rv[i] + 1e-5f);
        bias[i] = be[i] - s * rm[i];
    }
    for (int e = i; e < tot; e += gridDim.x * blockDim.x) {
        int o = e / cin, k = e - o * cin;
        float s = g[o] * rsqrtf(rv[o] + 1e-5f);
        wT[k * cout + o] = w[e] * s;
    }
}

// ------------------------- farthest point sampling -------------------------
template<int N, int NPOINT, int T>
__global__ void __launch_bounds__(T) fps_kernel(const float* __restrict__ xyz,
                                                float* __restrict__ newxyz)
{
    constexpr int PPT = N / T;
    int b = blockIdx.x;
    int tid = threadIdx.x;
    const float* x = xyz + (size_t)b * N * 3;

    float px[PPT], py[PPT], pz[PPT], dist[PPT];
#pragma unroll
    for (int i = 0; i < PPT; i++) {
        int p = tid + i * T;
        px[i] = x[p * 3 + 0];
        py[i] = x[p * 3 + 1];
        pz[i] = x[p * 3 + 2];
        dist[i] = 1e10f;
    }

    __shared__ float cur[3];
    __shared__ float wv[T / 32];
    __shared__ int   wi[T / 32];

    if (tid == 0) {
        cur[0] = x[0]; cur[1] = x[1]; cur[2] = x[2];
        float* o = newxyz + (size_t)b * NPOINT * 3;
        o[0] = x[0]; o[1] = x[1]; o[2] = x[2];
    }
    __syncthreads();

    for (int j = 1; j < NPOINT; j++) {
        float cx = cur[0], cy = cur[1], cz = cur[2];
        float bv = -1.0f;
        int   bi = 0x7fffffff;
#pragma unroll
        for (int i = 0; i < PPT; i++) {
            float dx = px[i] - cx, dy = py[i] - cy, dz = pz[i] - cz;
            float d = __fadd_rn(__fadd_rn(__fmul_rn(dx, dx), __fmul_rn(dy, dy)),
                                __fmul_rn(dz, dz));
            float nd = fminf(dist[i], d);
            dist[i] = nd;
            int gidx = tid + i * T;
            if (nd > bv || (nd == bv && gidx < bi)) { bv = nd; bi = gidx; }
        }
#pragma unroll
        for (int off = 16; off > 0; off >>= 1) {
            float ov = __shfl_down_sync(0xffffffffu, bv, off);
            int   oi = __shfl_down_sync(0xffffffffu, bi, off);
            if (ov > bv || (ov == bv && oi < bi)) { bv = ov; bi = oi; }
        }
        if ((tid & 31) == 0) { wv[tid >> 5] = bv; wi[tid >> 5] = bi; }
        __syncthreads();
        if (tid < 32) {
            constexpr int NW = T / 32;
            bv = (tid < NW) ? wv[tid] : -2.0f;
            bi = (tid < NW) ? wi[tid] : 0x7fffffff;
#pragma unroll
            for (int off = 16; off > 0; off >>= 1) {
                float ov = __shfl_down_sync(0xffffffffu, bv, off);
                int   oi = __shfl_down_sync(0xffffffffu, bi, off);
                if (ov > bv || (ov == bv && oi < bi)) { bv = ov; bi = oi; }
            }
            if (tid == 0) {
                const float* p = x + (size_t)bi * 3;
                float nx = p[0], ny = p[1], nz = p[2];
                cur[0] = nx; cur[1] = ny; cur[2] = nz;
                float* o = newxyz + ((size_t)b * NPOINT + j) * 3;
                o[0] = nx; o[1] = ny; o[2] = nz;
            }
        }
        __syncthreads();
    }
}

// ------------------------- ball query --------------------------------------
template<int NS>
__global__ void ballquery_kernel(const float* __restrict__ newxyz,
                                 const float* __restrict__ xyz,
                                 int* __restrict__ idxout,
                                 int N, int S, float rr)
{
    __shared__ int rows[4][NS];
    int lane = threadIdx.x & 31;
    int wip  = threadIdx.x >> 5;
    int q = blockIdx.x * 4 + wip;
    int b = q / S;
    const float* nq = newxyz + (size_t)q * 3;
    float qx = nq[0], qy = nq[1], qz = nq[2];
    const float* x = xyz + (size_t)b * N * 3;
    int* row = rows[wip];
    int cnt = 0;

    for (int base = 0; base < N; base += 32) {
        if (cnt >= NS) break;
        int p = base + lane;
        float dx = x[p * 3 + 0] - qx;
        float dy = x[p * 3 + 1] - qy;
        float dz = x[p * 3 + 2] - qz;
        float d = __fadd_rn(__fadd_rn(__fmul_rn(dx, dx), __fmul_rn(dy, dy)),
                            __fmul_rn(dz, dz));
        bool hit = d < rr;
        unsigned m = __ballot_sync(0xffffffffu, hit);
        if (hit) {
            int pos = cnt + __popc(m & ((1u << lane) - 1u));
            if (pos < NS) row[pos] = p;
        }
        cnt += __popc(m);
    }
    __syncwarp();
    int first = (cnt > 0) ? row[0] : 0;
    for (int t = cnt + lane; t < NS; t += 32) row[t] = first;
    __syncwarp();
    for (int t = lane; t < NS; t += 32) idxout[(size_t)q * NS + t] = row[t];
}

// ------------------------- fused group + MLP(2) + maxpool ------------------
// 2-D register tiling: each thread computes 4 output channels x NO samples.
// Per k: 1 LDG.128 (weights, k-major), NO/4 LDS.128 (samples, warp-broadcast),
// 2*NO FFMA2. Warp layout tid = n8*CQ + cq keeps sample reads broadcast.
template<int CIN, int C0, int C1, int NS, int T, int NO0, int NO1,
         bool STAGE0, bool FINAL>
__global__ void __launch_bounds__(T) sa_mlp_kernel(
    const float* __restrict__ xyz, const float* __restrict__ feats,
    const float* __restrict__ newxyz, const int* __restrict__ idx,
    const float* __restrict__ w0T, const float* __restrict__ b0,
    const float* __restrict__ w1T, const float* __restrict__ b1,
    float* __restrict__ out, int N, int S)
{
    constexpr int LD = NS + 4;                  // 16B-aligned row pitch
    __shared__ __align__(16) float xs[CIN * LD];
    __shared__ __align__(16) float mid[C0 * LD];

    int gs = blockIdx.x;
    int b = gs / S, s = gs - b * S;
    int tid = threadIdx.x;
    const int* gi = idx + (size_t)gs * NS;
    float cx = newxyz[gs * 3 + 0], cy = newxyz[gs * 3 + 1], cz = newxyz[gs * 3 + 2];

    // ---- gather ----
    for (int n = tid; n < NS; n += T) {
        int id = gi[n];
        const float* p = xyz + ((size_t)b * N + id) * 3;
        float ax = p[0], ay = p[1], az = p[2];
        xs[0 * LD + n] = ax - cx;
        xs[1 * LD + n] = ay - cy;
        xs[2 * LD + n] = az - cz;
        if (STAGE0) {
            xs[3 * LD + n] = ax; xs[4 * LD + n] = ay; xs[5 * LD + n] = az;
            xs[6 * LD + n] = ax; xs[7 * LD + n] = ay; xs[8 * LD + n] = az;
        }
    }
    if constexpr (!STAGE0) {
        constexpr int CF = CIN - 3;
        for (int e = tid; e < CF * NS; e += T) {
            int n = e / CF, c = e - n * CF;
            xs[(3 + c) * LD + n] = feats[((size_t)b * N + gi[n]) * CF + c];
        }
    }
    __syncthreads();

    // ---- layer 0: xs[CIN x NS] -> mid[C0 x NS], relu ----
    {
        constexpr int CQ = C0 / 4;
        constexpr int NGRP = NS / NO0;
        static_assert(CQ * NGRP == T, "layer0 thread mapping");
        int cq = tid % CQ;
        int n8 = tid / CQ;

        u64 acc[4][NO0 / 2];
        float4 bv = *reinterpret_cast<const float4*>(b0 + 4 * cq);
        {
            float bk[4] = {bv.x, bv.y, bv.z, bv.w};
#pragma unroll
            for (int i = 0; i < 4; i++) {
                u64 p = pack2(bk[i]);
#pragma unroll
                for (int j = 0; j < NO0 / 2; j++) acc[i][j] = p;
            }
        }
        const float* xrow = xs + n8 * NO0;
#pragma unroll 4
        for (int k = 0; k < CIN; k++) {
            float4 w = *reinterpret_cast<const float4*>(w0T + k * C0 + 4 * cq);
            ulonglong2 v[NO0 / 4];
            const ulonglong2* xr = reinterpret_cast<const ulonglong2*>(xrow + k * LD);
#pragma unroll
            for (int j = 0; j < NO0 / 4; j++) v[j] = xr[j];
            float wk[4] = {w.x, w.y, w.z, w.w};
#pragma unroll
            for (int i = 0; i < 4; i++) {
                u64 w2 = pack2(wk[i]);
#pragma unroll
                for (int j = 0; j < NO0 / 4; j++) {
                    acc[i][2 * j + 0] = ffma2(w2, v[j].x, acc[i][2 * j + 0]);
                    acc[i][2 * j + 1] = ffma2(w2, v[j].y, acc[i][2 * j + 1]);
                }
            }
        }
#pragma unroll
        for (int i = 0; i < 4; i++) {
            float* mrow = mid + (4 * cq + i) * LD + n8 * NO0;
#pragma unroll
            for (int j = 0; j < NO0 / 2; j++) {
                float lo, hi;
                unpack2(acc[i][j], lo, hi);
                mrow[2 * j + 0] = fmaxf(lo, 0.0f);
                mrow[2 * j + 1] = fmaxf(hi, 0.0f);
            }
        }
    }
    __syncthreads();

    // ---- layer 1: mid[C0 x NS] -> partial max over samples ----
    float* pmax = xs;                            // xs is dead now; reuse
    {
        constexpr int CQ = C1 / 4;
        constexpr int NGRP = NS / NO1;
        static_assert(CQ * NGRP == T, "layer1 thread mapping");
        int cq = tid % CQ;
        int n8 = tid / CQ;

        u64 acc[4][NO1 / 2];
        float4 bv = *reinterpret_cast<const float4*>(b1 + 4 * cq);
        {
            float bk[4] = {bv.x, bv.y, bv.z, bv.w};
#pragma unroll
            for (int i = 0; i < 4; i++) {
                u64 p = pack2(bk[i]);
#pragma unroll
                for (int j = 0; j < NO1 / 2; j++) acc[i][j] = p;
            }
        }
        const float* mrowb = mid + n8 * NO1;
#pragma unroll 4
        for (int k = 0; k < C0; k++) {
            float4 w = *reinterpret_cast<const float4*>(w1T + k * C1 + 4 * cq);
            ulonglong2 v[NO1 / 4];
            const ulonglong2* mr = reinterpret_cast<const ulonglong2*>(mrowb + k * LD);
#pragma unroll
            for (int j = 0; j < NO1 / 4; j++) v[j] = mr[j];
            float wk[4] = {w.x, w.y, w.z, w.w};
#pragma unroll
            for (int i = 0; i < 4; i++) {
                u64 w2 = pack2(wk[i]);
#pragma unroll
                for (int j = 0; j < NO1 / 4; j++) {
                    acc[i][2 * j + 0] = ffma2(w2, v[j].x, acc[i][2 * j + 0]);
                    acc[i][2 * j + 1] = ffma2(w2, v[j].y, acc[i][2 * j + 1]);
                }
            }
        }
#pragma unroll
        for (int i = 0; i < 4; i++) {
            float m = -3.4e38f;
#pragma unroll
            for (int j = 0; j < NO1 / 2; j++) {
                float lo, hi;
                unpack2(acc[i][j], lo, hi);
                m = fmaxf(m, fmaxf(lo, hi));
            }
            pmax[n8 * C1 + 4 * cq + i] = m;
        }
    }
    __syncthreads();

    // ---- final max across sample groups + relu + store ----
    {
        constexpr int NGRP = NS / NO1;
        for (int c = tid; c < C1; c += T) {       // strided: handles C1 > T
            float m = pmax[c];
#pragma unroll
            for (int g = 1; g < NGRP; g++) m = fmaxf(m, pmax[g * C1 + c]);
            m = fmaxf(m, 0.0f);
            if (FINAL)
                out[(size_t)b * C1 * S + (size_t)c * S + s] = m;  // (B, C, S)
            else
                out[((size_t)b * S + s) * C1 + c] = m;            // (B, S, C)
        }
    }
}

// ---------------------------------------------------------------------------
extern "C" void kernel_launch(void* const* d_in, const int* in_sizes, int n_in,
                              void* d_out, int out_size)
{
    (void)in_sizes; (void)n_in; (void)out_size;
    const float* pc = (const float*)d_in[0];

    float *nx1, *nx2, *nx3, *f1, *f2;
    int* idxb;
    float *w0T, *w1T, *w2T, *w3T, *w4T, *w5T;
    float *b0, *b1, *b2, *b3, *b4, *b5;
    cudaGetSymbolAddress((void**)&nx1, g_nx1);
    cudaGetSymbolAddress((void**)&nx2, g_nx2);
    cudaGetSymbolAddress((void**)&nx3, g_nx3);
    cudaGetSymbolAddress((void**)&idxb, g_idxbuf);
    cudaGetSymbolAddress((void**)&f1, g_f1);
    cudaGetSymbolAddress((void**)&f2, g_f2);
    cudaGetSymbolAddress((void**)&w0T, g_w0T); cudaGetSymbolAddress((void**)&b0, g_b0);
    cudaGetSymbolAddress((void**)&w1T, g_w1T); cudaGetSymbolAddress((void**)&b1, g_b1);
    cudaGetSymbolAddress((void**)&w2T, g_w2T); cudaGetSymbolAddress((void**)&b2, g_b2);
    cudaGetSymbolAddress((void**)&w3T, g_w3T); cudaGetSymbolAddress((void**)&b3, g_b3);
    cudaGetSymbolAddress((void**)&w4T, g_w4T); cudaGetSymbolAddress((void**)&b4, g_b4);
    cudaGetSymbolAddress((void**)&w5T, g_w5T); cudaGetSymbolAddress((void**)&b5, g_b5);

    FoldArgs fa;
    const int cins[6]  = {9, 32, 67, 128, 131, 256};
    const int couts[6] = {32, 64, 128, 128, 256, 256};
    float* wTs[6] = {w0T, w1T, w2T, w3T, w4T, w5T};
    float* bss[6] = {b0, b1, b2, b3, b4, b5};
    for (int l = 0; l < 6; l++) {
        fa.w[l]  = (const float*)d_in[1 + 5 * l];
        fa.g[l]  = (const float*)d_in[2 + 5 * l];
        fa.be[l] = (const float*)d_in[3 + 5 * l];
        fa.rm[l] = (const float*)d_in[4 + 5 * l];
        fa.rv[l] = (const float*)d_in[5 + 5 * l];
        fa.wT[l] = wTs[l]; fa.bias[l] = bss[l];
        fa.cin[l] = cins[l]; fa.cout[l] = couts[l];
    }
    fold_all_kernel<<<dim3(72, 6), 256>>>(fa);

    const float rr0 = (float)(0.02 * 0.02);
    const float rr1 = (float)(0.04 * 0.04);
    const float rr2 = (float)(0.08 * 0.08);

    // ---- stage 0: N=4096 -> S=128, 9->32->64, NS=32 ----
    fps_kernel<4096, 128, 256><<<B, 256>>>(pc, nx1);
    ballquery_kernel<32><<<(B * S0) / 4, 128>>>(nx1, pc, idxb, N0, S0, rr0);
    sa_mlp_kernel<9, 32, 64, 32, 64, 4, 8, true, false><<<B * S0, 64>>>(
        pc, nullptr, nx1, idxb, w0T, b0, w1T, b1, f1, N0, S0);

    // ---- stage 1: N=128 -> S=64, 67->128->128, NS=32 ----
    fps_kernel<128, 64, 128><<<B, 128>>>(nx1, nx2);
    ballquery_kernel<32><<<(B * S1) / 4, 128>>>(nx2, nx1, idxb, S0, S1, rr1);
    sa_mlp_kernel<67, 128, 128, 32, 128, 8, 8, false, false><<<B * S1, 128>>>(
        nx1, f1, nx2, idxb, w2T, b2, w3T, b3, f2, S0, S1);

    // ---- stage 2: N=64 -> S=32, 131->256->256, NS=16 ----
    fps_kernel<64, 32, 64><<<B, 64>>>(nx2, nx3);
    ballquery_kernel<16><<<(B * S2) / 4, 128>>>(nx3, nx2, idxb, S1, S2, rr2);
    sa_mlp_kernel<131, 256, 256, 16, 128, 8, 8, false, true><<<B * S2, 128>>>(
        nx2, f2, nx3, idxb, w4T, b4, w5T, b5, (float*)d_out, S1, S2);
}